// round 5
// baseline (speedup 1.0000x reference)
#include <cuda_runtime.h>
#include <cuda_bf16.h>

// ============================================================================
// ECE over N=2^24 samples, 15 bins — single fused kernel.
//   bin(c) = ceil(c*nb) - 1  for c in (0,1], else dropped
//   ece    = sum_b<nb | sum_{i in b} (conf_i - acc_i) | / n
//
// R5: BRANCHLESS bin update via unsigned-clamp overflow routing:
//   b = umin((unsigned)(f2i_ru(c*nb) - 1), 15)
// c<=0 wraps to huge -> bin 15; c>1 lands in bins >= nb; NaN -> bin 15.
// Bins >= nb are dropped in the final sum (reference overflow semantics).
// This cuts ~15 warp-instrs/element (incl. BSSY/BRA/BSYNC from the C++ if)
// to ~9, which is the real limiter (issue-bound at ~25% -> 4.5 TB/s plateau).
// Occupancy restored: launch_bounds(256,6), grid 1024, 2x float4 unroll.
// ============================================================================

#define TPB 256
#define MAX_BINS 16          // bins 0..nb-1 real, nb..15 = overflow (dropped)
#define NBLOCKS 1024
#define MAX_BLOCKS 4096

__device__ float g_partial[MAX_BLOCKS * MAX_BINS];
__device__ unsigned int g_count = 0;

__device__ __forceinline__ void bin_add(float* __restrict__ sb, int tid,
                                        float cf, float af, float fnb) {
    // ceil(c*nb)-1, clamped into [0,15] with invalids routed to overflow bins.
    int x = __float2int_ru(cf * fnb);
    unsigned int b = umin((unsigned int)(x - 1), (unsigned int)(MAX_BINS - 1));
    sb[b * TPB + tid] += cf - af;     // unconditional: overflow bins dropped later
}

__global__ __launch_bounds__(TPB, 6)
void ece_kernel(const float* __restrict__ conf,
                const float* __restrict__ acc,
                const int* __restrict__ num_bins_p,
                int n,
                float* __restrict__ out) {
    // Two DISTINCT arrays -> two provably-independent LDS->FADD->STS chains.
    __shared__ float sbA[MAX_BINS * TPB];   // 16 KB
    __shared__ float sbB[MAX_BINS * TPB];   // 16 KB
    const int tid = threadIdx.x;
    const int nb = *num_bins_p;
    const float fnb = (float)nb;

    #pragma unroll
    for (int b = 0; b < MAX_BINS; b++) {
        sbA[b * TPB + tid] = 0.0f;
        sbB[b * TPB + tid] = 0.0f;
    }
    __syncthreads();

    const int nvec = n >> 2;
    const float4* __restrict__ c4 = (const float4*)conf;
    const float4* __restrict__ a4 = (const float4*)acc;
    const int S = gridDim.x * blockDim.x;

    int i = blockIdx.x * blockDim.x + tid;
    // 2x unrolled grid-stride: 4 front-batched LDG.128 per iteration.
    for (; i + S < nvec; i += 2 * S) {
        const float4 c0 = __ldg(&c4[i]);
        const float4 c1 = __ldg(&c4[i + S]);
        const float4 a0 = __ldg(&a4[i]);
        const float4 a1 = __ldg(&a4[i + S]);
        bin_add(sbA, tid, c0.x, a0.x, fnb);
        bin_add(sbB, tid, c0.y, a0.y, fnb);
        bin_add(sbA, tid, c0.z, a0.z, fnb);
        bin_add(sbB, tid, c0.w, a0.w, fnb);
        bin_add(sbA, tid, c1.x, a1.x, fnb);
        bin_add(sbB, tid, c1.y, a1.y, fnb);
        bin_add(sbA, tid, c1.z, a1.z, fnb);
        bin_add(sbB, tid, c1.w, a1.w, fnb);
    }
    for (; i < nvec; i += S) {
        const float4 c = __ldg(&c4[i]);
        const float4 a = __ldg(&a4[i]);
        bin_add(sbA, tid, c.x, a.x, fnb);
        bin_add(sbB, tid, c.y, a.y, fnb);
        bin_add(sbA, tid, c.z, a.z, fnb);
        bin_add(sbB, tid, c.w, a.w, fnb);
    }
    // scalar remainder (n not multiple of 4): block 0 only
    if (blockIdx.x == 0) {
        for (int j = (nvec << 2) + tid; j < n; j += blockDim.x)
            bin_add(sbA, tid, conf[j], acc[j], fnb);
    }
    __syncthreads();

    // merge B into A (conflict-free), then tree-reduce the 256 lane copies
    #pragma unroll
    for (int b = 0; b < MAX_BINS; b++)
        sbA[b * TPB + tid] += sbB[b * TPB + tid];
    __syncthreads();

    for (int s = TPB / 2; s > 0; s >>= 1) {
        if (tid < s) {
            #pragma unroll
            for (int b = 0; b < MAX_BINS; b++)
                sbA[b * TPB + tid] += sbA[b * TPB + tid + s];
        }
        __syncthreads();
    }

    if (tid < MAX_BINS)
        g_partial[blockIdx.x * MAX_BINS + tid] = sbA[tid * TPB];

    // ---- last-block tail reduction (no second launch) ----
    __shared__ bool is_last;
    __threadfence();
    if (tid == 0) {
        unsigned int ticket = atomicAdd(&g_count, 1u);
        is_last = (ticket == gridDim.x - 1);
    }
    __syncthreads();

    if (is_last) {
        __threadfence();
        // element e -> bin (e & 15); stride 256 keeps bin = tid & 15 constant
        const int total = gridDim.x * MAX_BINS;
        float s = 0.0f;
        for (int e = tid; e < total; e += TPB)
            s += g_partial[e];

        __shared__ float red[TPB];
        red[tid] = s;
        __syncthreads();

        if (tid < MAX_BINS) {
            float t = 0.0f;
            #pragma unroll
            for (int k = 0; k < TPB / MAX_BINS; k++)
                t += red[tid + k * MAX_BINS];
            red[tid] = fabsf(t);
        }
        __syncthreads();

        if (tid == 0) {
            float tot = 0.0f;
            for (int b = 0; b < nb; b++)    // ONLY bins < nb: overflow dropped
                tot += red[b];
            out[0] = tot / (float)n;
            g_count = 0;                    // reset for next graph replay
        }
    }
}

extern "C" void kernel_launch(void* const* d_in, const int* in_sizes, int n_in,
                              void* d_out, int out_size) {
    const float* conf = (const float*)d_in[0];
    const float* acc  = (const float*)d_in[1];
    const int*   nbp  = (const int*)d_in[2];
    float* out = (float*)d_out;
    const int n = in_sizes[0];

    int nvec = n >> 2;
    int blocks = (nvec + TPB - 1) / TPB;
    if (blocks > NBLOCKS) blocks = NBLOCKS;
    if (blocks < 1) blocks = 1;

    ece_kernel<<<blocks, TPB>>>(conf, acc, nbp, n, out);
}

// round 6
// speedup vs baseline: 1.2752x; 1.2752x over previous
#include <cuda_runtime.h>
#include <cuda_bf16.h>

// ============================================================================
// ECE over N=2^24 samples, 15 bins — single fused kernel.
//   bin(c) = ceil(c*nb) - 1  for c in (0,1], else dropped
//   ece    = sum_{b<nb} | sum_{i in b} (conf_i - acc_i) | / n
//
// R6 = R2/R3 skeleton (ONE 16KB bin array, 4x unroll -> 8 front-batched
// LDG.128, grid 1024) + lean branchless bin math (~9 instr/elem):
//   b = umin((unsigned)(f2i_ru(c*nb) - 1), 15)   // invalid -> bin 15, dropped
// Evidence: R5 regressed purely from halving the load batch (MLP 8->4);
// occupancy beyond ~43% is not needed (R3==R2). This round combines
// MLP=8 + occ~62% + lean math for the first time.
// ============================================================================

#define TPB 256
#define MAX_BINS 16          // bins 0..nb-1 real, nb..15 overflow (dropped)
#define NBLOCKS 1024         // 2^18 threads -> 16 vec4/thread, no tail
#define MAX_BLOCKS 4096

__device__ float g_partial[MAX_BLOCKS * MAX_BINS];
__device__ unsigned int g_count = 0;

__device__ __forceinline__ void bin_add(float* __restrict__ sb, int tid,
                                        float cf, float af, float fnb) {
    // ceil(c*nb)-1 with unsigned-wrap clamp: c<=0 wraps huge -> 15; c>1 -> 15;
    // NaN -> f2i=0 -> wrap -> 15. Bin 15 (and any bin >= nb) dropped later.
    unsigned int b = umin((unsigned int)(__float2int_ru(cf * fnb) - 1),
                          (unsigned int)(MAX_BINS - 1));
    sb[b * TPB + tid] += cf - af;
}

__global__ __launch_bounds__(TPB, 5)   // 51 regs: real 8-deep LDG.128 batch
void ece_kernel(const float* __restrict__ conf,
                const float* __restrict__ acc,
                const int* __restrict__ num_bins_p,
                int n,
                float* __restrict__ out) {
    __shared__ float sb[MAX_BINS * TPB];   // 16 KB, per-lane private bins
    const int tid = threadIdx.x;
    const int nb = *num_bins_p;
    const float fnb = (float)nb;

    #pragma unroll
    for (int b = 0; b < MAX_BINS; b++)
        sb[b * TPB + tid] = 0.0f;
    __syncthreads();

    const int nvec = n >> 2;
    const float4* __restrict__ c4 = (const float4*)conf;
    const float4* __restrict__ a4 = (const float4*)acc;
    const int S = gridDim.x * blockDim.x;

    int i = blockIdx.x * blockDim.x + tid;
    // 4x unrolled grid-stride: 8 front-batched LDG.128 per iteration
    for (; i + 3 * S < nvec; i += 4 * S) {
        const float4 c0 = __ldg(&c4[i]);
        const float4 c1 = __ldg(&c4[i + S]);
        const float4 c2 = __ldg(&c4[i + 2 * S]);
        const float4 c3 = __ldg(&c4[i + 3 * S]);
        const float4 a0 = __ldg(&a4[i]);
        const float4 a1 = __ldg(&a4[i + S]);
        const float4 a2 = __ldg(&a4[i + 2 * S]);
        const float4 a3 = __ldg(&a4[i + 3 * S]);
        bin_add(sb, tid, c0.x, a0.x, fnb);
        bin_add(sb, tid, c0.y, a0.y, fnb);
        bin_add(sb, tid, c0.z, a0.z, fnb);
        bin_add(sb, tid, c0.w, a0.w, fnb);
        bin_add(sb, tid, c1.x, a1.x, fnb);
        bin_add(sb, tid, c1.y, a1.y, fnb);
        bin_add(sb, tid, c1.z, a1.z, fnb);
        bin_add(sb, tid, c1.w, a1.w, fnb);
        bin_add(sb, tid, c2.x, a2.x, fnb);
        bin_add(sb, tid, c2.y, a2.y, fnb);
        bin_add(sb, tid, c2.z, a2.z, fnb);
        bin_add(sb, tid, c2.w, a2.w, fnb);
        bin_add(sb, tid, c3.x, a3.x, fnb);
        bin_add(sb, tid, c3.y, a3.y, fnb);
        bin_add(sb, tid, c3.z, a3.z, fnb);
        bin_add(sb, tid, c3.w, a3.w, fnb);
    }
    for (; i < nvec; i += S) {
        const float4 c = __ldg(&c4[i]);
        const float4 a = __ldg(&a4[i]);
        bin_add(sb, tid, c.x, a.x, fnb);
        bin_add(sb, tid, c.y, a.y, fnb);
        bin_add(sb, tid, c.z, a.z, fnb);
        bin_add(sb, tid, c.w, a.w, fnb);
    }
    // scalar remainder (n not multiple of 4): block 0 only
    if (blockIdx.x == 0) {
        for (int j = (nvec << 2) + tid; j < n; j += blockDim.x)
            bin_add(sb, tid, conf[j], acc[j], fnb);
    }
    __syncthreads();

    // tree-reduce the 256 per-lane copies (addr stride 4B -> conflict-free)
    for (int s = TPB / 2; s > 0; s >>= 1) {
        if (tid < s) {
            #pragma unroll
            for (int b = 0; b < MAX_BINS; b++)
                sb[b * TPB + tid] += sb[b * TPB + tid + s];
        }
        __syncthreads();
    }

    if (tid < MAX_BINS)
        g_partial[blockIdx.x * MAX_BINS + tid] = sb[tid * TPB];

    // ---- last-block tail reduction (no second launch) ----
    __shared__ bool is_last;
    __threadfence();
    if (tid == 0) {
        unsigned int ticket = atomicAdd(&g_count, 1u);
        is_last = (ticket == gridDim.x - 1);
    }
    __syncthreads();

    if (is_last) {
        __threadfence();
        // element e -> bin (e & 15); stride 256 keeps bin = tid & 15 constant
        const int total = gridDim.x * MAX_BINS;
        float s = 0.0f;
        for (int e = tid; e < total; e += TPB)
            s += g_partial[e];

        __shared__ float red[TPB];
        red[tid] = s;
        __syncthreads();

        if (tid < MAX_BINS) {
            float t = 0.0f;
            #pragma unroll
            for (int k = 0; k < TPB / MAX_BINS; k++)
                t += red[tid + k * MAX_BINS];
            red[tid] = fabsf(t);
        }
        __syncthreads();

        if (tid == 0) {
            float tot = 0.0f;
            for (int b = 0; b < nb; b++)    // ONLY bins < nb: overflow dropped
                tot += red[b];
            out[0] = tot / (float)n;
            g_count = 0;                    // reset for next graph replay
        }
    }
}

extern "C" void kernel_launch(void* const* d_in, const int* in_sizes, int n_in,
                              void* d_out, int out_size) {
    const float* conf = (const float*)d_in[0];
    const float* acc  = (const float*)d_in[1];
    const int*   nbp  = (const int*)d_in[2];
    float* out = (float*)d_out;
    const int n = in_sizes[0];

    int nvec = n >> 2;
    int blocks = (nvec + TPB - 1) / TPB;
    if (blocks > NBLOCKS) blocks = NBLOCKS;
    if (blocks < 1) blocks = 1;

    ece_kernel<<<blocks, TPB>>>(conf, acc, nbp, n, out);
}

// round 7
// speedup vs baseline: 1.3821x; 1.0838x over previous
#include <cuda_runtime.h>
#include <cuda_bf16.h>

// ============================================================================
// ECE over N=2^24 samples, 15 bins — single fused kernel.
//   bin(c) = ceil(c*nb) - 1  for c in (0,1], else dropped
//   ece    = sum_{b<nb} | sum_{i in b} (conf_i - acc_i) | / n
//
// R7: TPB=128. smem/block halves to 8KB -> 8 CTAs/SM (32 warps, occ 50%)
// at 64 regs, which finally gives ptxas room to keep the full 8-deep
// LDG.128 batch live (at 48 regs it staged the batch, MLP_eff ~3-4).
// Lean branchless bin math (unsigned-clamp overflow routing, ~9 instr/elem),
// __ldcs streaming loads (zero reuse), fused last-block tail reduction.
// ============================================================================

#define TPB 128
#define MAX_BINS 16          // bins 0..nb-1 real, nb..15 overflow (dropped)
#define NBLOCKS 1024         // 2^17 threads -> 32 vec4/thread, no tail
#define MAX_BLOCKS 4096

__device__ float g_partial[MAX_BLOCKS * MAX_BINS];
__device__ unsigned int g_count = 0;

__device__ __forceinline__ void bin_add(float* __restrict__ sb, int tid,
                                        float cf, float af, float fnb) {
    // ceil(c*nb)-1 with unsigned-wrap clamp: c<=0 wraps huge -> 15; c>1 lands
    // in bins >= nb; NaN -> f2i 0 -> wrap -> 15. Overflow bins dropped later.
    unsigned int b = umin((unsigned int)(__float2int_ru(cf * fnb) - 1),
                          (unsigned int)(MAX_BINS - 1));
    sb[b * TPB + tid] += cf - af;
}

__global__ __launch_bounds__(TPB, 8)   // 64 regs, 8 CTAs/SM, 32 warps
void ece_kernel(const float* __restrict__ conf,
                const float* __restrict__ acc,
                const int* __restrict__ num_bins_p,
                int n,
                float* __restrict__ out) {
    __shared__ float sb[MAX_BINS * TPB];   // 8 KB, per-lane private bins
    const int tid = threadIdx.x;
    const int nb = *num_bins_p;
    const float fnb = (float)nb;

    #pragma unroll
    for (int b = 0; b < MAX_BINS; b++)
        sb[b * TPB + tid] = 0.0f;
    __syncthreads();

    const int nvec = n >> 2;
    const float4* __restrict__ c4 = (const float4*)conf;
    const float4* __restrict__ a4 = (const float4*)acc;
    const int S = gridDim.x * blockDim.x;

    int i = blockIdx.x * blockDim.x + tid;
    // 4x unrolled grid-stride: 8 front-batched streaming LDG.128 per iter
    for (; i + 3 * S < nvec; i += 4 * S) {
        const float4 c0 = __ldcs(&c4[i]);
        const float4 c1 = __ldcs(&c4[i + S]);
        const float4 c2 = __ldcs(&c4[i + 2 * S]);
        const float4 c3 = __ldcs(&c4[i + 3 * S]);
        const float4 a0 = __ldcs(&a4[i]);
        const float4 a1 = __ldcs(&a4[i + S]);
        const float4 a2 = __ldcs(&a4[i + 2 * S]);
        const float4 a3 = __ldcs(&a4[i + 3 * S]);
        bin_add(sb, tid, c0.x, a0.x, fnb);
        bin_add(sb, tid, c0.y, a0.y, fnb);
        bin_add(sb, tid, c0.z, a0.z, fnb);
        bin_add(sb, tid, c0.w, a0.w, fnb);
        bin_add(sb, tid, c1.x, a1.x, fnb);
        bin_add(sb, tid, c1.y, a1.y, fnb);
        bin_add(sb, tid, c1.z, a1.z, fnb);
        bin_add(sb, tid, c1.w, a1.w, fnb);
        bin_add(sb, tid, c2.x, a2.x, fnb);
        bin_add(sb, tid, c2.y, a2.y, fnb);
        bin_add(sb, tid, c2.z, a2.z, fnb);
        bin_add(sb, tid, c2.w, a2.w, fnb);
        bin_add(sb, tid, c3.x, a3.x, fnb);
        bin_add(sb, tid, c3.y, a3.y, fnb);
        bin_add(sb, tid, c3.z, a3.z, fnb);
        bin_add(sb, tid, c3.w, a3.w, fnb);
    }
    for (; i < nvec; i += S) {
        const float4 c = __ldcs(&c4[i]);
        const float4 a = __ldcs(&a4[i]);
        bin_add(sb, tid, c.x, a.x, fnb);
        bin_add(sb, tid, c.y, a.y, fnb);
        bin_add(sb, tid, c.z, a.z, fnb);
        bin_add(sb, tid, c.w, a.w, fnb);
    }
    // scalar remainder (n not multiple of 4): block 0 only
    if (blockIdx.x == 0) {
        for (int j = (nvec << 2) + tid; j < n; j += blockDim.x)
            bin_add(sb, tid, conf[j], acc[j], fnb);
    }
    __syncthreads();

    // tree-reduce the 128 per-lane copies (addr stride 4B -> conflict-free)
    for (int s = TPB / 2; s > 0; s >>= 1) {
        if (tid < s) {
            #pragma unroll
            for (int b = 0; b < MAX_BINS; b++)
                sb[b * TPB + tid] += sb[b * TPB + tid + s];
        }
        __syncthreads();
    }

    if (tid < MAX_BINS)
        g_partial[blockIdx.x * MAX_BINS + tid] = sb[tid * TPB];

    // ---- last-block tail reduction (no second launch) ----
    __shared__ bool is_last;
    __threadfence();
    if (tid == 0) {
        unsigned int ticket = atomicAdd(&g_count, 1u);
        is_last = (ticket == gridDim.x - 1);
    }
    __syncthreads();

    if (is_last) {
        __threadfence();
        // element e -> bin (e & 15); stride 128 keeps bin = tid & 15 constant
        const int total = gridDim.x * MAX_BINS;
        float s = 0.0f;
        for (int e = tid; e < total; e += TPB)
            s += g_partial[e];

        __shared__ float red[TPB];
        red[tid] = s;
        __syncthreads();

        if (tid < MAX_BINS) {
            float t = 0.0f;
            #pragma unroll
            for (int k = 0; k < TPB / MAX_BINS; k++)
                t += red[tid + k * MAX_BINS];
            red[tid] = fabsf(t);
        }
        __syncthreads();

        if (tid == 0) {
            float tot = 0.0f;
            for (int b = 0; b < nb; b++)    // ONLY bins < nb: overflow dropped
                tot += red[b];
            out[0] = tot / (float)n;
            g_count = 0;                    // reset for next graph replay
        }
    }
}

extern "C" void kernel_launch(void* const* d_in, const int* in_sizes, int n_in,
                              void* d_out, int out_size) {
    const float* conf = (const float*)d_in[0];
    const float* acc  = (const float*)d_in[1];
    const int*   nbp  = (const int*)d_in[2];
    float* out = (float*)d_out;
    const int n = in_sizes[0];

    int nvec = n >> 2;
    int blocks = (nvec + TPB - 1) / TPB;
    if (blocks > NBLOCKS) blocks = NBLOCKS;
    if (blocks < 1) blocks = 1;

    ece_kernel<<<blocks, TPB>>>(conf, acc, nbp, n, out);
}

// round 8
// speedup vs baseline: 1.4529x; 1.0512x over previous
#include <cuda_runtime.h>
#include <cuda_bf16.h>

// ============================================================================
// ECE over N=2^24 samples, 15 bins — single fused kernel.
//   bin(c) = ceil(c*nb) - 1  for c in (0,1], else dropped
//   ece    = sum_{b<nb} | sum_{i in b} (conf_i - acc_i) | / n
//
// R8 = R4's fast-warp loop (explicit register double-buffer prefetch hides
// LDG latency behind the shared RMW chain; TWO split shared arrays halve the
// aliasing-ordered LDS->FADD->STS chain) at REAL occupancy this time:
// TPB=128 (8KB/array -> 16KB smem/CTA), launch_bounds(128,7) -> 73 regs,
// 7 CTAs/SM = 28 warps. R4's per-warp rate was 1.5x R3's; it lost only
// because the grid capped it at 2 CTAs/SM. Lean branchless bin math (R5).
// ============================================================================

#define TPB 128
#define MAX_BINS 16          // bins 0..nb-1 real, nb..15 overflow (dropped)
#define NBLOCKS 1024
#define MAX_BLOCKS 4096

__device__ float g_partial[MAX_BLOCKS * MAX_BINS];
__device__ unsigned int g_count = 0;

__device__ __forceinline__ void bin_add(float* __restrict__ sb, int tid,
                                        float cf, float af, float fnb) {
    // ceil(c*nb)-1 with unsigned-wrap clamp: c<=0 wraps huge -> 15; c>1 lands
    // in bins >= nb; NaN -> f2i 0 -> wrap -> 15. Overflow bins dropped later.
    unsigned int b = umin((unsigned int)(__float2int_ru(cf * fnb) - 1),
                          (unsigned int)(MAX_BINS - 1));
    sb[b * TPB + tid] += cf - af;
}

__global__ __launch_bounds__(TPB, 7)   // 73 regs: holds the double buffer
void ece_kernel(const float* __restrict__ conf,
                const float* __restrict__ acc,
                const int* __restrict__ num_bins_p,
                int n,
                float* __restrict__ out) {
    // Two DISTINCT arrays -> two independent RMW chains (x,z vs y,w).
    __shared__ float sbA[MAX_BINS * TPB];   // 8 KB
    __shared__ float sbB[MAX_BINS * TPB];   // 8 KB
    const int tid = threadIdx.x;
    const int nb = *num_bins_p;
    const float fnb = (float)nb;

    #pragma unroll
    for (int b = 0; b < MAX_BINS; b++) {
        sbA[b * TPB + tid] = 0.0f;
        sbB[b * TPB + tid] = 0.0f;
    }
    __syncthreads();

    const int nvec = n >> 2;
    const float4* __restrict__ c4 = (const float4*)conf;
    const float4* __restrict__ a4 = (const float4*)acc;
    const int S = gridDim.x * blockDim.x;

    int i = blockIdx.x * blockDim.x + tid;

    float4 c0, c1, c2, c3, a0, a1, a2, a3;
    bool have = (i + 3 * S < nvec);
    if (have) {
        c0 = __ldcs(&c4[i]);         c1 = __ldcs(&c4[i + S]);
        c2 = __ldcs(&c4[i + 2 * S]); c3 = __ldcs(&c4[i + 3 * S]);
        a0 = __ldcs(&a4[i]);         a1 = __ldcs(&a4[i + S]);
        a2 = __ldcs(&a4[i + 2 * S]); a3 = __ldcs(&a4[i + 3 * S]);
    }
    while (have) {
        const int inext = i + 4 * S;
        const bool have_next = (inext + 3 * S < nvec);
        float4 nc0, nc1, nc2, nc3, na0, na1, na2, na3;
        if (have_next) {            // prefetch NEXT batch before the chain
            nc0 = __ldcs(&c4[inext]);         nc1 = __ldcs(&c4[inext + S]);
            nc2 = __ldcs(&c4[inext + 2 * S]); nc3 = __ldcs(&c4[inext + 3 * S]);
            na0 = __ldcs(&a4[inext]);         na1 = __ldcs(&a4[inext + S]);
            na2 = __ldcs(&a4[inext + 2 * S]); na3 = __ldcs(&a4[inext + 3 * S]);
        }
        // x,z -> sbA ; y,w -> sbB : two interleavable 8-element chains
        bin_add(sbA, tid, c0.x, a0.x, fnb);
        bin_add(sbB, tid, c0.y, a0.y, fnb);
        bin_add(sbA, tid, c0.z, a0.z, fnb);
        bin_add(sbB, tid, c0.w, a0.w, fnb);
        bin_add(sbA, tid, c1.x, a1.x, fnb);
        bin_add(sbB, tid, c1.y, a1.y, fnb);
        bin_add(sbA, tid, c1.z, a1.z, fnb);
        bin_add(sbB, tid, c1.w, a1.w, fnb);
        bin_add(sbA, tid, c2.x, a2.x, fnb);
        bin_add(sbB, tid, c2.y, a2.y, fnb);
        bin_add(sbA, tid, c2.z, a2.z, fnb);
        bin_add(sbB, tid, c2.w, a2.w, fnb);
        bin_add(sbA, tid, c3.x, a3.x, fnb);
        bin_add(sbB, tid, c3.y, a3.y, fnb);
        bin_add(sbA, tid, c3.z, a3.z, fnb);
        bin_add(sbB, tid, c3.w, a3.w, fnb);

        c0 = nc0; c1 = nc1; c2 = nc2; c3 = nc3;
        a0 = na0; a1 = na1; a2 = na2; a3 = na3;
        i = inext;
        have = have_next;
    }
    // vec4 tail
    for (; i < nvec; i += S) {
        const float4 c = __ldcs(&c4[i]);
        const float4 a = __ldcs(&a4[i]);
        bin_add(sbA, tid, c.x, a.x, fnb);
        bin_add(sbB, tid, c.y, a.y, fnb);
        bin_add(sbA, tid, c.z, a.z, fnb);
        bin_add(sbB, tid, c.w, a.w, fnb);
    }
    // scalar remainder (n not multiple of 4): block 0 only
    if (blockIdx.x == 0) {
        for (int j = (nvec << 2) + tid; j < n; j += blockDim.x)
            bin_add(sbA, tid, conf[j], acc[j], fnb);
    }
    __syncthreads();

    // merge B into A, then tree-reduce the 128 lane copies (conflict-free)
    #pragma unroll
    for (int b = 0; b < MAX_BINS; b++)
        sbA[b * TPB + tid] += sbB[b * TPB + tid];
    __syncthreads();

    for (int s = TPB / 2; s > 0; s >>= 1) {
        if (tid < s) {
            #pragma unroll
            for (int b = 0; b < MAX_BINS; b++)
                sbA[b * TPB + tid] += sbA[b * TPB + tid + s];
        }
        __syncthreads();
    }

    if (tid < MAX_BINS)
        g_partial[blockIdx.x * MAX_BINS + tid] = sbA[tid * TPB];

    // ---- last-block tail reduction (no second launch) ----
    __shared__ bool is_last;
    __threadfence();
    if (tid == 0) {
        unsigned int ticket = atomicAdd(&g_count, 1u);
        is_last = (ticket == gridDim.x - 1);
    }
    __syncthreads();

    if (is_last) {
        __threadfence();
        // element e -> bin (e & 15); stride 128 keeps bin = tid & 15 constant
        const int total = gridDim.x * MAX_BINS;
        float s = 0.0f;
        for (int e = tid; e < total; e += TPB)
            s += g_partial[e];

        __shared__ float red[TPB];
        red[tid] = s;
        __syncthreads();

        if (tid < MAX_BINS) {
            float t = 0.0f;
            #pragma unroll
            for (int k = 0; k < TPB / MAX_BINS; k++)
                t += red[tid + k * MAX_BINS];
            red[tid] = fabsf(t);
        }
        __syncthreads();

        if (tid == 0) {
            float tot = 0.0f;
            for (int b = 0; b < nb; b++)    // ONLY bins < nb: overflow dropped
                tot += red[b];
            out[0] = tot / (float)n;
            g_count = 0;                    // reset for next graph replay
        }
    }
}

extern "C" void kernel_launch(void* const* d_in, const int* in_sizes, int n_in,
                              void* d_out, int out_size) {
    const float* conf = (const float*)d_in[0];
    const float* acc  = (const float*)d_in[1];
    const int*   nbp  = (const int*)d_in[2];
    float* out = (float*)d_out;
    const int n = in_sizes[0];

    int nvec = n >> 2;
    int blocks = (nvec + TPB - 1) / TPB;
    if (blocks > NBLOCKS) blocks = NBLOCKS;
    if (blocks < 1) blocks = 1;

    ece_kernel<<<blocks, TPB>>>(conf, acc, nbp, n, out);
}